// round 6
// baseline (speedup 1.0000x reference)
#include <cuda_runtime.h>
#include <math.h>

#define BATCH  2
#define SEQLEN 2048
#define H      512
#define NST    64
#define M      8           // compressed modes per channel
#define MP     4           // mode pairs (f32x2)
#define K      64          // time chunks
#define TCH    32          // SEQLEN / K

typedef unsigned long long u64;

// compressed coefficient tables, pair-packed, [pair j][h] (coalesced over h)
__device__ u64 g_a2[MP * H];
__device__ u64 g_c2[MP * H];
__device__ u64 g_q2[MP * H];
// end-of-chunk states / chunk-entry carries: [b][k][j][h]
__device__ u64 g_zend[BATCH * K * MP * H];
__device__ u64 g_S[BATCH * K * MP * H];

__device__ __forceinline__ u64 pack2(float lo, float hi) {
    u64 r; asm("mov.b64 %0, {%1, %2};" : "=l"(r) : "f"(lo), "f"(hi)); return r;
}
__device__ __forceinline__ void unpack2(u64 v, float& lo, float& hi) {
    asm("mov.b64 {%0, %1}, %2;" : "=f"(lo), "=f"(hi) : "l"(v));
}
__device__ __forceinline__ u64 fma2_(u64 a, u64 b, u64 c) {
    u64 d; asm("fma.rn.f32x2 %0, %1, %2, %3;" : "=l"(d) : "l"(a), "l"(b), "l"(c)); return d;
}
__device__ __forceinline__ u64 add2_(u64 a, u64 b) {
    u64 d; asm("add.rn.f32x2 %0, %1, %2;" : "=l"(d) : "l"(a), "l"(b)); return d;
}

// ---------------------------------------------------------------- precompute
// Chebyshev-node mode compression: 64 true modes -> 8 virtual modes.
// Each block (64 threads) builds the Lagrange table ell[n][m] in smem (double),
// then each thread finishes one channel h.
__global__ void s4_precomp(const float* __restrict__ B_re,
                           const float* __restrict__ C_re,
                           const float* __restrict__ log_dt)
{
    __shared__ double ell[NST][M];
    __shared__ double snode[M];

    const int tid = threadIdx.x;        // 0..63

    // Chebyshev nodes over the true A-range [rsqrt(2), rsqrt(1+1/64)]
    const double lo = 0.70710678118654752440;                 // 1/sqrt(2)
    const double hi = 0.99227787671366762912;                 // rsqrt(65/64)
    const double ctr = 0.5 * (lo + hi), hwd = 0.5 * (hi - lo);
    double node[M];
#pragma unroll
    for (int m = 0; m < M; ++m)
        node[m] = ctr + hwd * cos(3.14159265358979323846 * (2 * m + 1) / (2.0 * M));
    if (tid < M) snode[tid] = node[tid];

    // Lagrange basis values at the 64 true A_n
    {
        const double An = 1.0 / sqrt(1.0 + (double)(tid + 1) / (double)NST);
#pragma unroll
        for (int m = 0; m < M; ++m) {
            double num = 1.0, den = 1.0;
#pragma unroll
            for (int i = 0; i < M; ++i) {
                if (i == m) continue;
                num *= (An - node[i]);
                den *= (node[m] - node[i]);
            }
            ell[tid][m] = num / den;
        }
    }
    __syncthreads();

    const int h = blockIdx.x * 64 + tid;
    const float delta = expf(log_dt[h]);

    float ct[M];
#pragma unroll
    for (int m = 0; m < M; ++m) ct[m] = 0.0f;

    for (int n = 0; n < NST; ++n) {
        const float A  = rsqrtf(1.0f + (float)(n + 1) * (1.0f / NST));
        const float dA = delta * A;
        const float cn = expm1f(dA) * B_re[n] * delta * C_re[n];
#pragma unroll
        for (int m = 0; m < M; ++m)
            ct[m] = fmaf(cn, (float)ell[n][m], ct[m]);
    }

    float am[M], qm[M];
#pragma unroll
    for (int m = 0; m < M; ++m) {
        const float dAm = delta * (float)snode[m];
        am[m] = expf(dAm);
        qm[m] = expf(dAm * (float)TCH);
    }
#pragma unroll
    for (int j = 0; j < MP; ++j) {
        g_a2[j * H + h] = pack2(am[2 * j], am[2 * j + 1]);
        g_c2[j * H + h] = pack2(ct[2 * j], ct[2 * j + 1]);
        g_q2[j * H + h] = pack2(qm[2 * j], qm[2 * j + 1]);
    }
}

// ------------------------------------------------------------------ pass 1
// State-only local scan per (b, hw, k) with 8 virtual modes.
__global__ __launch_bounds__(128, 8)
void s4_pass1(const float* __restrict__ u)
{
    const int w    = threadIdx.x >> 5;
    const int lane = threadIdx.x & 31;
    const int gw   = blockIdx.x * 4 + w;      // 2048 warps
    const int k  = gw & (K - 1);
    const int hw = (gw >> 6) & 15;
    const int b  = gw >> 10;
    const int h  = hw * 32 + lane;

    u64 a[MP], z[MP];
#pragma unroll
    for (int j = 0; j < MP; ++j) { a[j] = g_a2[j * H + h]; z[j] = 0ull; }

    const float* ub = u + ((size_t)b * SEQLEN + (size_t)k * TCH) * H + h;

    float up[8];
#pragma unroll
    for (int s = 0; s < 8; ++s) up[s] = ub[(size_t)s * H];

    for (int t = 0; t < TCH; t += 8) {
        float uc[8];
#pragma unroll
        for (int s = 0; s < 8; ++s) uc[s] = up[s];
        if (t + 8 < TCH) {
            const float* p = ub + (size_t)(t + 8) * H;
#pragma unroll
            for (int s = 0; s < 8; ++s) up[s] = p[(size_t)s * H];
        }
#pragma unroll
        for (int s = 0; s < 8; ++s) {
            const u64 ubb = pack2(uc[s], uc[s]);
#pragma unroll
            for (int j = 0; j < MP; ++j)
                z[j] = fma2_(a[j], z[j], ubb);
        }
    }

    u64* zo = g_zend + ((size_t)(b * K + k) * MP) * H + h;
#pragma unroll
    for (int j = 0; j < MP; ++j) zo[(size_t)j * H] = z[j];
}

// ------------------------------------------------------------------ carry
// Prefix over chunks: S_{k} = q S_{k-1} + zend_{k-1}, batched prefetch (MLP=16).
__global__ __launch_bounds__(128, 4)
void s4_carry()
{
    const int w    = threadIdx.x >> 5;
    const int lane = threadIdx.x & 31;
    const int gw   = blockIdx.x * 4 + w;      // 128 warps
    const int j  = gw & (MP - 1);
    const int hw = (gw >> 2) & 15;
    const int b  = gw >> 6;
    const int h  = hw * 32 + lane;

    const u64 q = g_q2[j * H + h];
    const u64* zp = g_zend + ((size_t)(b * K) * MP + j) * H + h;
    u64*       Sp = g_S    + ((size_t)(b * K) * MP + j) * H + h;

    u64 S = 0ull;
    for (int kb = 0; kb < K; kb += 16) {
        u64 zz[16];
#pragma unroll
        for (int i = 0; i < 16; ++i)
            zz[i] = zp[(size_t)(kb + i) * MP * H];
#pragma unroll
        for (int i = 0; i < 16; ++i) {
            const int k = kb + i;              // consumes zend[k] -> S[k+1]
            if (k + 1 < K) {
                S = fma2_(q, S, zz[i]);
                Sp[(size_t)(k + 1) * MP * H] = S;
            }
        }
    }
}

// ------------------------------------------------------------------ pass 2
// Full scan with 8 virtual modes, seeded with true chunk-entry state.
__global__ __launch_bounds__(128, 8)
void s4_pass2(const float* __restrict__ u,
              const float* __restrict__ Dp,
              float* __restrict__ y)
{
    const int w    = threadIdx.x >> 5;
    const int lane = threadIdx.x & 31;
    const int gw   = blockIdx.x * 4 + w;      // 2048 warps
    const int k  = gw & (K - 1);
    const int hw = (gw >> 6) & 15;
    const int b  = gw >> 10;
    const int h  = hw * 32 + lane;

    u64 a[MP], c[MP], z[MP];
#pragma unroll
    for (int j = 0; j < MP; ++j) {
        a[j] = g_a2[j * H + h];
        c[j] = g_c2[j * H + h];
    }
    if (k > 0) {
        const u64* Sp = g_S + ((size_t)(b * K + k) * MP) * H + h;
#pragma unroll
        for (int j = 0; j < MP; ++j) z[j] = Sp[(size_t)j * H];
    } else {
#pragma unroll
        for (int j = 0; j < MP; ++j) z[j] = 0ull;
    }
    const float Dh = Dp[h];

    const size_t base = ((size_t)b * SEQLEN + (size_t)k * TCH) * H + h;
    const float* ub = u + base;
    float*       yb = y + base;

    float up0 = ub[0 * H], up1 = ub[1 * H], up2 = ub[2 * H], up3 = ub[3 * H];

    for (int t = 0; t < TCH; t += 4) {
        float uc[4] = {up0, up1, up2, up3};
        if (t + 4 < TCH) {
            const float* p = ub + (size_t)(t + 4) * H;
            up0 = p[0 * H]; up1 = p[1 * H]; up2 = p[2 * H]; up3 = p[3 * H];
        }
#pragma unroll
        for (int s = 0; s < 4; ++s) {
            const float ut = uc[s];
            const u64 ubb = pack2(ut, ut);
            z[0] = fma2_(a[0], z[0], ubb);
            z[1] = fma2_(a[1], z[1], ubb);
            z[2] = fma2_(a[2], z[2], ubb);
            z[3] = fma2_(a[3], z[3], ubb);
            u64 ac0 = fma2_(c[0], z[0], 0ull);
            u64 ac1 = fma2_(c[1], z[1], 0ull);
            ac0 = fma2_(c[2], z[2], ac0);
            ac1 = fma2_(c[3], z[3], ac1);
            const u64 sS = add2_(ac0, ac1);
            float x0, x1; unpack2(sS, x0, x1);
            yb[(size_t)(t + s) * H] = fmaf(Dh, ut, x0 + x1);
        }
    }
}

extern "C" void kernel_launch(void* const* d_in, const int* in_sizes, int n_in,
                              void* d_out, int out_size)
{
    const float* u      = (const float*)d_in[0];
    const float* B_re   = (const float*)d_in[1];
    const float* C_re   = (const float*)d_in[2];
    const float* log_dt = (const float*)d_in[3];
    const float* Dp     = (const float*)d_in[4];
    float* y = (float*)d_out;

    s4_precomp<<<H / 64, 64>>>(B_re, C_re, log_dt);
    s4_pass1<<<(BATCH * 16 * K) / 4, 128>>>(u);
    s4_carry<<<(BATCH * 16 * MP) / 4, 128>>>();
    s4_pass2<<<(BATCH * 16 * K) / 4, 128>>>(u, Dp, y);
}

// round 7
// speedup vs baseline: 1.2340x; 1.2340x over previous
#include <cuda_runtime.h>
#include <math.h>

#define BATCH  2
#define SEQLEN 2048
#define H      512
#define NST    64
#define M      8           // virtual (compressed) modes
#define MP     4           // mode pairs (f32x2)
#define TCH    32          // timesteps per chunk (= per warp)
#define NWARP  8           // warps per CTA = chunks per group
#define NGRP   8           // chunk groups per (b,hw) column
#define NCOL   (BATCH * 16) // 32 columns; column = (b, hw)

typedef unsigned long long u64;

// compressed coefficient tables, pair-packed, [pair j][h]
__device__ u64 g_a2[MP * H];
__device__ u64 g_c2[MP * H];
__device__ u64 g_q2[MP * H];
// cross-group carries: [col][g][j][lane]
__device__ u64 g_S2[NCOL * NGRP * MP * 32];
// one flag per carry link, padded to 128B to avoid false sharing
__device__ int g_flag[NCOL * NGRP * 32];

__constant__ double d_node[M] = {
    0.989538141, 0.968247871, 0.928912736, 0.877509475,
    0.821875183, 0.770471922, 0.731136787, 0.709846517
};

__device__ __forceinline__ u64 pack2(float lo, float hi) {
    u64 r; asm("mov.b64 %0, {%1, %2};" : "=l"(r) : "f"(lo), "f"(hi)); return r;
}
__device__ __forceinline__ void unpack2(u64 v, float& lo, float& hi) {
    asm("mov.b64 {%0, %1}, %2;" : "=f"(lo), "=f"(hi) : "l"(v));
}
__device__ __forceinline__ u64 fma2_(u64 a, u64 b, u64 c) {
    u64 d; asm("fma.rn.f32x2 %0, %1, %2, %3;" : "=l"(d) : "l"(a), "l"(b), "l"(c)); return d;
}
__device__ __forceinline__ u64 mul2_(u64 a, u64 b) {
    u64 d; asm("mul.rn.f32x2 %0, %1, %2;" : "=l"(d) : "l"(a), "l"(b)); return d;
}
__device__ __forceinline__ u64 add2_(u64 a, u64 b) {
    u64 d; asm("add.rn.f32x2 %0, %1, %2;" : "=l"(d) : "l"(a), "l"(b)); return d;
}
__device__ __forceinline__ int ld_acq(const int* p) {
    int v; asm volatile("ld.acquire.gpu.s32 %0, [%1];" : "=r"(v) : "l"(p) : "memory"); return v;
}
__device__ __forceinline__ void st_rel(int* p, int v) {
    asm volatile("st.release.gpu.s32 [%0], %1;" :: "l"(p), "r"(v) : "memory");
}

// ---------------------------------------------------------------- precompute
// One block per channel h (512 blocks x 64 threads). Chebyshev 8-node mode
// compression: c~[m] = sum_n c_n * ell_m(A_n); a~/q~ = exp(delta*node[m]*{1,TCH}).
__global__ void s4_precomp(const float* __restrict__ B_re,
                           const float* __restrict__ C_re,
                           const float* __restrict__ log_dt)
{
    __shared__ float sc[M][NST + 1];
    __shared__ float sa[M], sq[M], scc[M];

    const int n = threadIdx.x;      // 0..63 (true mode)
    const int h = blockIdx.x;

    const float delta = expf(log_dt[h]);
    const double An = 1.0 / sqrt(1.0 + (double)(n + 1) / 64.0);
    const float cn = expm1f(delta * (float)An) * B_re[n] * delta * C_re[n];

#pragma unroll
    for (int m = 0; m < M; ++m) {
        double num = 1.0, den = 1.0;
#pragma unroll
        for (int i = 0; i < M; ++i) {
            if (i == m) continue;
            num *= (An - d_node[i]);
            den *= (d_node[m] - d_node[i]);
        }
        sc[m][n] = cn * (float)(num / den);
    }
    __syncthreads();

    if (n < M) {
        float s = 0.0f;
        for (int i = 0; i < NST; ++i) s += sc[n][i];
        scc[n] = s;
        const float dAm = delta * (float)d_node[n];
        sa[n] = expf(dAm);
        sq[n] = expf(dAm * (float)TCH);
    }
    __syncthreads();

    if (n < MP) {
        g_a2[n * H + h] = pack2(sa[2 * n], sa[2 * n + 1]);
        g_c2[n * H + h] = pack2(scc[2 * n], scc[2 * n + 1]);
        g_q2[n * H + h] = pack2(sq[2 * n], sq[2 * n + 1]);
    }
}

// ------------------------------------------------------------------ fused
// CTA = (column, group); warp w handles chunk g*8+w (32 timesteps), u kept in
// registers. Intra-CTA prefix via smem; cross-group carry via release/acquire
// flag chain (writer bid < reader bid; all 256 CTAs co-resident at occ 2).
__global__ __launch_bounds__(256, 2)
void s4_fused(const float* __restrict__ u,
              const float* __restrict__ Dp,
              float* __restrict__ y)
{
    __shared__ u64 sE[NWARP][MP][32];
    __shared__ u64 sS[MP][32];

    const int col  = blockIdx.x & (NCOL - 1);   // (b, hw)
    const int g    = blockIdx.x / NCOL;         // chunk group (bid-ordered!)
    const int w    = threadIdx.x >> 5;
    const int lane = threadIdx.x & 31;
    const int b    = col >> 4;
    const int h    = (col & 15) * 32 + lane;

    u64 a[MP], c[MP], q[MP];
#pragma unroll
    for (int j = 0; j < MP; ++j) {
        a[j] = g_a2[j * H + h];
        c[j] = g_c2[j * H + h];
        q[j] = g_q2[j * H + h];
    }
    const float Dh = Dp[h];

    const int chunk = g * NWARP + w;
    const size_t base = ((size_t)b * SEQLEN + (size_t)chunk * TCH) * H + h;
    const float* ub = u + base;

    // whole chunk of u into registers (32 coalesced LDGs, high MLP)
    float uu[TCH];
#pragma unroll
    for (int t = 0; t < TCH; ++t) uu[t] = ub[(size_t)t * H];

    // local zero-seed scan -> E (chunk impulse state)
    u64 z[MP] = {0ull, 0ull, 0ull, 0ull};
#pragma unroll
    for (int t = 0; t < TCH; ++t) {
        const u64 ubb = pack2(uu[t], uu[t]);
        z[0] = fma2_(a[0], z[0], ubb);
        z[1] = fma2_(a[1], z[1], ubb);
        z[2] = fma2_(a[2], z[2], ubb);
        z[3] = fma2_(a[3], z[3], ubb);
    }
#pragma unroll
    for (int j = 0; j < MP; ++j) sE[w][j][lane] = z[j];
    __syncthreads();

    // P_w = sum_{j2<w} q^{w-1-j2} E_{j2}  (Horner)
    u64 P[MP] = {0ull, 0ull, 0ull, 0ull};
    for (int j2 = 0; j2 < w; ++j2) {
#pragma unroll
        for (int j = 0; j < MP; ++j)
            P[j] = fma2_(q[j], P[j], sE[j2][j][lane]);
    }
    // qp = q^w
    u64 qp[MP];
#pragma unroll
    for (int j = 0; j < MP; ++j) qp[j] = pack2(1.0f, 1.0f);
    for (int i = 0; i < w; ++i) {
#pragma unroll
        for (int j = 0; j < MP; ++j) qp[j] = mul2_(qp[j], q[j]);
    }

    // warp 7: receive carry, publish next carry, stage S_in to smem
    if (w == NWARP - 1) {
        u64 Sin[MP];
        if (g > 0) {
            int* fp = &g_flag[(col * NGRP + (g - 1)) * 32];
            while (ld_acq(fp) == 0) { }
            const u64* sp = g_S2 + ((size_t)(col * NGRP + (g - 1)) * MP) * 32 + lane;
#pragma unroll
            for (int j = 0; j < MP; ++j) Sin[j] = sp[(size_t)j * 32];
            __syncwarp();
            if (lane == 0) *fp = 0;      // reset for next graph replay
        } else {
#pragma unroll
            for (int j = 0; j < MP; ++j) Sin[j] = 0ull;
        }
#pragma unroll
        for (int j = 0; j < MP; ++j) sS[j][lane] = Sin[j];

        if (g < NGRP - 1) {
            u64* op = g_S2 + ((size_t)(col * NGRP + g) * MP) * 32 + lane;
#pragma unroll
            for (int j = 0; j < MP; ++j) {
                const u64 q2v = mul2_(q[j], q[j]);
                const u64 q4v = mul2_(q2v, q2v);
                const u64 q8v = mul2_(q4v, q4v);
                const u64 R   = fma2_(q[j], P[j], z[j]);   // full-group transfer
                op[(size_t)j * 32] = fma2_(q8v, Sin[j], R);
            }
            __threadfence();
            __syncwarp();
            if (lane == 0) st_rel(&g_flag[(col * NGRP + g) * 32], 1);
        }
    }
    __syncthreads();

    // seed = q^w * S_in + P_w, then output scan (writes y exactly once)
    u64 zz[MP];
#pragma unroll
    for (int j = 0; j < MP; ++j) zz[j] = fma2_(qp[j], sS[j][lane], P[j]);

    float* yb = y + base;
#pragma unroll
    for (int t = 0; t < TCH; ++t) {
        const u64 ubb = pack2(uu[t], uu[t]);
        zz[0] = fma2_(a[0], zz[0], ubb);
        zz[1] = fma2_(a[1], zz[1], ubb);
        zz[2] = fma2_(a[2], zz[2], ubb);
        zz[3] = fma2_(a[3], zz[3], ubb);
        u64 ac0 = fma2_(c[0], zz[0], 0ull);
        u64 ac1 = fma2_(c[1], zz[1], 0ull);
        ac0 = fma2_(c[2], zz[2], ac0);
        ac1 = fma2_(c[3], zz[3], ac1);
        const u64 sSum = add2_(ac0, ac1);
        float x0, x1; unpack2(sSum, x0, x1);
        yb[(size_t)t * H] = fmaf(Dh, uu[t], x0 + x1);
    }
}

extern "C" void kernel_launch(void* const* d_in, const int* in_sizes, int n_in,
                              void* d_out, int out_size)
{
    const float* u      = (const float*)d_in[0];
    const float* B_re   = (const float*)d_in[1];
    const float* C_re   = (const float*)d_in[2];
    const float* log_dt = (const float*)d_in[3];
    const float* Dp     = (const float*)d_in[4];
    float* y = (float*)d_out;

    s4_precomp<<<H, NST>>>(B_re, C_re, log_dt);
    s4_fused<<<NCOL * NGRP, 256>>>(u, Dp, y);
}

// round 8
// speedup vs baseline: 1.4590x; 1.1824x over previous
#include <cuda_runtime.h>
#include <math.h>

#define BATCH  2
#define SEQLEN 2048
#define H      512
#define NST    64
#define M      8           // virtual (compressed) modes
#define MP     4           // mode pairs (f32x2)
#define TCH    32          // timesteps per chunk (= per warp)
#define NWARP  8           // warps per CTA = chunks per group
#define NGRP   8           // chunk groups per (b,hw) column
#define NCOL   (BATCH * 16) // 32 columns; column = (b, hw)

typedef unsigned long long u64;

// compressed coefficient tables, pair-packed, [pair j][h]
__device__ u64 g_a2[MP * H];
__device__ u64 g_c2[MP * H];
__device__ u64 g_q2[MP * H];
// per-group aggregates: [col][g][j][lane]
__device__ u64 g_R[NCOL * NGRP * MP * 32];
// one flag per (col, g), padded to 128B
__device__ int g_flag[NCOL * NGRP * 32];

__constant__ double d_node[M] = {
    0.989538141, 0.968247871, 0.928912736, 0.877509475,
    0.821875183, 0.770471922, 0.731136787, 0.709846517
};

__device__ __forceinline__ u64 pack2(float lo, float hi) {
    u64 r; asm("mov.b64 %0, {%1, %2};" : "=l"(r) : "f"(lo), "f"(hi)); return r;
}
__device__ __forceinline__ void unpack2(u64 v, float& lo, float& hi) {
    asm("mov.b64 {%0, %1}, %2;" : "=f"(lo), "=f"(hi) : "l"(v));
}
__device__ __forceinline__ u64 fma2_(u64 a, u64 b, u64 c) {
    u64 d; asm("fma.rn.f32x2 %0, %1, %2, %3;" : "=l"(d) : "l"(a), "l"(b), "l"(c)); return d;
}
__device__ __forceinline__ u64 mul2_(u64 a, u64 b) {
    u64 d; asm("mul.rn.f32x2 %0, %1, %2;" : "=l"(d) : "l"(a), "l"(b)); return d;
}
__device__ __forceinline__ u64 add2_(u64 a, u64 b) {
    u64 d; asm("add.rn.f32x2 %0, %1, %2;" : "=l"(d) : "l"(a), "l"(b)); return d;
}
__device__ __forceinline__ int ld_acq(const int* p) {
    int v; asm volatile("ld.acquire.gpu.s32 %0, [%1];" : "=r"(v) : "l"(p) : "memory"); return v;
}
__device__ __forceinline__ void st_rel(int* p, int v) {
    asm volatile("st.release.gpu.s32 [%0], %1;" :: "l"(p), "r"(v) : "memory");
}

// ---------------------------------------------------------------- precompute
// One block per channel h. Also resets the carry flags (stream-ordered before
// the fused kernel, so flags are clean on every graph replay).
__global__ void s4_precomp(const float* __restrict__ B_re,
                           const float* __restrict__ C_re,
                           const float* __restrict__ log_dt)
{
    __shared__ float sc[M][NST + 1];
    __shared__ float sa[M], sq[M], scc[M];

    const int n = threadIdx.x;      // 0..63 (true mode)
    const int h = blockIdx.x;

    if (h == 0) {
        for (int i = n; i < NCOL * NGRP; i += NST)
            g_flag[i * 32] = 0;
    }

    const float delta = expf(log_dt[h]);
    const double An = 1.0 / sqrt(1.0 + (double)(n + 1) / 64.0);
    const float cn = expm1f(delta * (float)An) * B_re[n] * delta * C_re[n];

#pragma unroll
    for (int m = 0; m < M; ++m) {
        double num = 1.0, den = 1.0;
#pragma unroll
        for (int i = 0; i < M; ++i) {
            if (i == m) continue;
            num *= (An - d_node[i]);
            den *= (d_node[m] - d_node[i]);
        }
        sc[m][n] = cn * (float)(num / den);
    }
    __syncthreads();

    if (n < M) {
        float s = 0.0f;
        for (int i = 0; i < NST; ++i) s += sc[n][i];
        scc[n] = s;
        const float dAm = delta * (float)d_node[n];
        sa[n] = expf(dAm);
        sq[n] = expf(dAm * (float)TCH);
    }
    __syncthreads();

    if (n < MP) {
        g_a2[n * H + h] = pack2(sa[2 * n], sa[2 * n + 1]);
        g_c2[n * H + h] = pack2(scc[2 * n], scc[2 * n + 1]);
        g_q2[n * H + h] = pack2(sq[2 * n], sq[2 * n + 1]);
    }
}

// ------------------------------------------------------------------ fused
// CTA = (column, group); warp w = chunk g*8+w (32 timesteps), u in registers.
// Parallel carry: every CTA publishes its OWN group aggregate R_g right after
// its local scan (no chaining); group g combines R_0..R_{g-1} with one Horner.
// Critical path = local scan + ONE publish->receive hop + output scan.
__global__ __launch_bounds__(256, 2)
void s4_fused(const float* __restrict__ u,
              const float* __restrict__ Dp,
              float* __restrict__ y)
{
    __shared__ u64 sE[NWARP][MP][32];
    __shared__ u64 sS[MP][32];

    const int col  = blockIdx.x & (NCOL - 1);   // (b, hw)
    const int g    = blockIdx.x >> 5;           // group; lower g = lower bid
    const int w    = threadIdx.x >> 5;
    const int lane = threadIdx.x & 31;
    const int b    = col >> 4;
    const int h    = (col & 15) * 32 + lane;

    u64 a[MP], c[MP], q[MP];
#pragma unroll
    for (int j = 0; j < MP; ++j) {
        a[j] = g_a2[j * H + h];
        c[j] = g_c2[j * H + h];
        q[j] = g_q2[j * H + h];
    }
    const float Dh = Dp[h];

    const int chunk = g * NWARP + w;
    const size_t base = ((size_t)b * SEQLEN + (size_t)chunk * TCH) * H + h;
    const float* ub = u + base;

    // whole chunk of u into registers (32 coalesced LDGs, MLP=32)
    float uu[TCH];
#pragma unroll
    for (int t = 0; t < TCH; ++t) uu[t] = ub[(size_t)t * H];

    // local zero-seed scan -> E (chunk impulse state)
    u64 z[MP] = {0ull, 0ull, 0ull, 0ull};
#pragma unroll
    for (int t = 0; t < TCH; ++t) {
        const u64 ubb = pack2(uu[t], uu[t]);
        z[0] = fma2_(a[0], z[0], ubb);
        z[1] = fma2_(a[1], z[1], ubb);
        z[2] = fma2_(a[2], z[2], ubb);
        z[3] = fma2_(a[3], z[3], ubb);
    }
#pragma unroll
    for (int j = 0; j < MP; ++j) sE[w][j][lane] = z[j];
    __syncthreads();

    // P_w = sum_{i<w} q^{w-1-i} E_i  (intra-group Horner over smem)
    u64 P[MP] = {0ull, 0ull, 0ull, 0ull};
    for (int i = 0; i < w; ++i) {
#pragma unroll
        for (int j = 0; j < MP; ++j)
            P[j] = fma2_(q[j], P[j], sE[i][j][lane]);
    }
    // qp = q^w
    u64 qp[MP];
#pragma unroll
    for (int j = 0; j < MP; ++j) qp[j] = pack2(1.0f, 1.0f);
    for (int i = 0; i < w; ++i) {
#pragma unroll
        for (int j = 0; j < MP; ++j) qp[j] = mul2_(qp[j], q[j]);
    }

    // warp 7: publish this group's aggregate R = q*P_7 + E_7 (independent of
    // other groups -> all publishes happen in parallel)
    if (w == NWARP - 1 && g < NGRP - 1) {
        u64* op = g_R + ((size_t)(col * NGRP + g) * MP) * 32 + lane;
#pragma unroll
        for (int j = 0; j < MP; ++j)
            op[(size_t)j * 32] = fma2_(q[j], P[j], z[j]);
        __threadfence();
        __syncwarp();
        if (lane == 0) st_rel(&g_flag[(col * NGRP + g) * 32], 1);
    }

    // warp 0: receive all prior groups' aggregates, combine with q^8 Horner
    if (w == 0) {
        u64 S[MP] = {0ull, 0ull, 0ull, 0ull};
        if (g > 0) {
            for (int g2 = 0; g2 < g; ++g2) {
                const int* fp = &g_flag[(col * NGRP + g2) * 32];
                while (ld_acq(fp) == 0) { }
            }
            __syncwarp();
            u64 q8[MP];
#pragma unroll
            for (int j = 0; j < MP; ++j) {
                const u64 q2v = mul2_(q[j], q[j]);
                const u64 q4v = mul2_(q2v, q2v);
                q8[j] = mul2_(q4v, q4v);
            }
            for (int g2 = 0; g2 < g; ++g2) {
                const u64* rp = g_R + ((size_t)(col * NGRP + g2) * MP) * 32 + lane;
#pragma unroll
                for (int j = 0; j < MP; ++j)
                    S[j] = fma2_(q8[j], S[j], rp[(size_t)j * 32]);
            }
        }
#pragma unroll
        for (int j = 0; j < MP; ++j) sS[j][lane] = S[j];
    }
    __syncthreads();

    // seed = q^w * S_in + P_w, then output scan (writes y exactly once)
    u64 zz[MP];
#pragma unroll
    for (int j = 0; j < MP; ++j) zz[j] = fma2_(qp[j], sS[j][lane], P[j]);

    float* yb = y + base;
#pragma unroll
    for (int t = 0; t < TCH; ++t) {
        const u64 ubb = pack2(uu[t], uu[t]);
        zz[0] = fma2_(a[0], zz[0], ubb);
        zz[1] = fma2_(a[1], zz[1], ubb);
        zz[2] = fma2_(a[2], zz[2], ubb);
        zz[3] = fma2_(a[3], zz[3], ubb);
        u64 ac0 = fma2_(c[0], zz[0], 0ull);
        u64 ac1 = fma2_(c[1], zz[1], 0ull);
        ac0 = fma2_(c[2], zz[2], ac0);
        ac1 = fma2_(c[3], zz[3], ac1);
        const u64 sSum = add2_(ac0, ac1);
        float x0, x1; unpack2(sSum, x0, x1);
        yb[(size_t)t * H] = fmaf(Dh, uu[t], x0 + x1);
    }
}

extern "C" void kernel_launch(void* const* d_in, const int* in_sizes, int n_in,
                              void* d_out, int out_size)
{
    const float* u      = (const float*)d_in[0];
    const float* B_re   = (const float*)d_in[1];
    const float* C_re   = (const float*)d_in[2];
    const float* log_dt = (const float*)d_in[3];
    const float* Dp     = (const float*)d_in[4];
    float* y = (float*)d_out;

    s4_precomp<<<H, NST>>>(B_re, C_re, log_dt);
    s4_fused<<<NCOL * NGRP, 256>>>(u, Dp, y);
}

// round 9
// speedup vs baseline: 3.0169x; 2.0678x over previous
#include <cuda_runtime.h>
#include <math.h>

#define BATCH  2
#define SEQLEN 2048
#define H      512
#define NST    64
#define M      8           // virtual (compressed) modes
#define MP     4           // mode pairs (f32x2)
#define TCH    32          // timesteps per chunk (= per warp)
#define NWARP  8           // warps per CTA = chunks per group
#define NGRP   8           // chunk groups per (b,hw) column
#define NCOL   (BATCH * 16) // 32 columns; column = (b, hw)

typedef unsigned long long u64;

// compressed coefficient tables, pair-packed, [pair j][h]
__device__ u64 g_a2[MP * H];
__device__ u64 g_c2[MP * H];
__device__ u64 g_q2[MP * H];
// per-group aggregates: [col][g][j][lane]
__device__ u64 g_R[NCOL * NGRP * MP * 32];
// one flag per (col, g), padded to 128B
__device__ int g_flag[NCOL * NGRP * 32];

// Chebyshev nodes over [rsqrt(2), rsqrt(65/64)] (fixed problem constants)
__constant__ float f_node[M] = {
    0.989538141f, 0.968247871f, 0.928912736f, 0.877509475f,
    0.821875183f, 0.770471922f, 0.731136787f, 0.709846517f
};

__device__ __forceinline__ u64 pack2(float lo, float hi) {
    u64 r; asm("mov.b64 %0, {%1, %2};" : "=l"(r) : "f"(lo), "f"(hi)); return r;
}
__device__ __forceinline__ void unpack2(u64 v, float& lo, float& hi) {
    asm("mov.b64 {%0, %1}, %2;" : "=f"(lo), "=f"(hi) : "l"(v));
}
__device__ __forceinline__ u64 fma2_(u64 a, u64 b, u64 c) {
    u64 d; asm("fma.rn.f32x2 %0, %1, %2, %3;" : "=l"(d) : "l"(a), "l"(b), "l"(c)); return d;
}
__device__ __forceinline__ u64 mul2_(u64 a, u64 b) {
    u64 d; asm("mul.rn.f32x2 %0, %1, %2;" : "=l"(d) : "l"(a), "l"(b)); return d;
}
__device__ __forceinline__ u64 add2_(u64 a, u64 b) {
    u64 d; asm("add.rn.f32x2 %0, %1, %2;" : "=l"(d) : "l"(a), "l"(b)); return d;
}
__device__ __forceinline__ int ld_acq(const int* p) {
    int v; asm volatile("ld.acquire.gpu.s32 %0, [%1];" : "=r"(v) : "l"(p) : "memory"); return v;
}
__device__ __forceinline__ void st_rel(int* p, int v) {
    asm volatile("st.release.gpu.s32 [%0], %1;" :: "l"(p), "r"(v) : "memory");
}

// ---------------------------------------------------------------- precompute
// One block per channel h; ALL FLOAT (fp64 Lagrange math was ~15us of the
// round-8 runtime). Also resets carry flags (stream-ordered before fused).
__global__ void s4_precomp(const float* __restrict__ B_re,
                           const float* __restrict__ C_re,
                           const float* __restrict__ log_dt)
{
    __shared__ float sc[M][NST + 1];
    __shared__ float sa[M], sq[M], scc[M];

    const int n = threadIdx.x;      // 0..63 (true mode)
    const int h = blockIdx.x;

    if (h == 0) {
        for (int i = n; i < NCOL * NGRP; i += NST)
            g_flag[i * 32] = 0;
    }

    const float delta = expf(log_dt[h]);
    const float An = rsqrtf(1.0f + (float)(n + 1) * (1.0f / 64.0f));
    const float cn = expm1f(delta * An) * B_re[n] * delta * C_re[n];

#pragma unroll
    for (int m = 0; m < M; ++m) {
        float num = 1.0f, den = 1.0f;
#pragma unroll
        for (int i = 0; i < M; ++i) {
            if (i == m) continue;
            num *= (An - f_node[i]);
            den *= (f_node[m] - f_node[i]);
        }
        sc[m][n] = cn * (num / den);
    }
    __syncthreads();

    if (n < M) {
        float s = 0.0f;
#pragma unroll
        for (int i = 0; i < NST; ++i) s += sc[n][i];
        scc[n] = s;
        const float dAm = delta * f_node[n];
        sa[n] = expf(dAm);
        sq[n] = expf(dAm * (float)TCH);
    }
    __syncthreads();

    if (n < MP) {
        g_a2[n * H + h] = pack2(sa[2 * n], sa[2 * n + 1]);
        g_c2[n * H + h] = pack2(scc[2 * n], scc[2 * n + 1]);
        g_q2[n * H + h] = pack2(sq[2 * n], sq[2 * n + 1]);
    }
}

// ------------------------------------------------------------------ fused
// CTA = (column, group); warp w = chunk g*8+w (32 timesteps), u in registers.
// Parallel carry: every CTA publishes its OWN group aggregate R_g right after
// its local scan; group g combines R_0..R_{g-1} with one q^8-Horner.
__global__ __launch_bounds__(256, 2)
void s4_fused(const float* __restrict__ u,
              const float* __restrict__ Dp,
              float* __restrict__ y)
{
    __shared__ u64 sE[NWARP][MP][32];
    __shared__ u64 sS[MP][32];

    const int col  = blockIdx.x & (NCOL - 1);   // (b, hw)
    const int g    = blockIdx.x >> 5;           // group; lower g = lower bid
    const int w    = threadIdx.x >> 5;
    const int lane = threadIdx.x & 31;
    const int b    = col >> 4;
    const int h    = (col & 15) * 32 + lane;

    u64 a[MP], c[MP], q[MP];
#pragma unroll
    for (int j = 0; j < MP; ++j) {
        a[j] = g_a2[j * H + h];
        c[j] = g_c2[j * H + h];
        q[j] = g_q2[j * H + h];
    }
    const float Dh = Dp[h];

    const int chunk = g * NWARP + w;
    const size_t base = ((size_t)b * SEQLEN + (size_t)chunk * TCH) * H + h;
    const float* ub = u + base;

    // whole chunk of u into registers (32 coalesced LDGs, MLP=32)
    float uu[TCH];
#pragma unroll
    for (int t = 0; t < TCH; ++t) uu[t] = ub[(size_t)t * H];

    // local zero-seed scan -> E (chunk impulse state)
    u64 z[MP] = {0ull, 0ull, 0ull, 0ull};
#pragma unroll
    for (int t = 0; t < TCH; ++t) {
        const u64 ubb = pack2(uu[t], uu[t]);
        z[0] = fma2_(a[0], z[0], ubb);
        z[1] = fma2_(a[1], z[1], ubb);
        z[2] = fma2_(a[2], z[2], ubb);
        z[3] = fma2_(a[3], z[3], ubb);
    }
#pragma unroll
    for (int j = 0; j < MP; ++j) sE[w][j][lane] = z[j];
    __syncthreads();

    // P_w = sum_{i<w} q^{w-1-i} E_i  (intra-group Horner over smem)
    u64 P[MP] = {0ull, 0ull, 0ull, 0ull};
    for (int i = 0; i < w; ++i) {
#pragma unroll
        for (int j = 0; j < MP; ++j)
            P[j] = fma2_(q[j], P[j], sE[i][j][lane]);
    }
    // qp = q^w
    u64 qp[MP];
#pragma unroll
    for (int j = 0; j < MP; ++j) qp[j] = pack2(1.0f, 1.0f);
    for (int i = 0; i < w; ++i) {
#pragma unroll
        for (int j = 0; j < MP; ++j) qp[j] = mul2_(qp[j], q[j]);
    }

    // warp 7: publish this group's aggregate R = q*P_7 + E_7
    // (st.release orders the prior g_R stores; no separate fence needed)
    if (w == NWARP - 1 && g < NGRP - 1) {
        u64* op = g_R + ((size_t)(col * NGRP + g) * MP) * 32 + lane;
#pragma unroll
        for (int j = 0; j < MP; ++j)
            op[(size_t)j * 32] = fma2_(q[j], P[j], z[j]);
        __syncwarp();
        if (lane == 0) st_rel(&g_flag[(col * NGRP + g) * 32], 1);
    }

    // warp 0: receive all prior groups' aggregates, combine with q^8 Horner
    if (w == 0) {
        u64 S[MP] = {0ull, 0ull, 0ull, 0ull};
        if (g > 0) {
            for (int g2 = 0; g2 < g; ++g2) {
                const int* fp = &g_flag[(col * NGRP + g2) * 32];
                while (ld_acq(fp) == 0) { __nanosleep(32); }
            }
            __syncwarp();
            u64 q8[MP];
#pragma unroll
            for (int j = 0; j < MP; ++j) {
                const u64 q2v = mul2_(q[j], q[j]);
                const u64 q4v = mul2_(q2v, q2v);
                q8[j] = mul2_(q4v, q4v);
            }
            for (int g2 = 0; g2 < g; ++g2) {
                const u64* rp = g_R + ((size_t)(col * NGRP + g2) * MP) * 32 + lane;
#pragma unroll
                for (int j = 0; j < MP; ++j)
                    S[j] = fma2_(q8[j], S[j], rp[(size_t)j * 32]);
            }
        }
#pragma unroll
        for (int j = 0; j < MP; ++j) sS[j][lane] = S[j];
    }
    __syncthreads();

    // seed = q^w * S_in + P_w, then output scan (writes y exactly once)
    u64 zz[MP];
#pragma unroll
    for (int j = 0; j < MP; ++j) zz[j] = fma2_(qp[j], sS[j][lane], P[j]);

    float* yb = y + base;
#pragma unroll
    for (int t = 0; t < TCH; ++t) {
        const u64 ubb = pack2(uu[t], uu[t]);
        zz[0] = fma2_(a[0], zz[0], ubb);
        zz[1] = fma2_(a[1], zz[1], ubb);
        zz[2] = fma2_(a[2], zz[2], ubb);
        zz[3] = fma2_(a[3], zz[3], ubb);
        u64 ac0 = fma2_(c[0], zz[0], 0ull);
        u64 ac1 = fma2_(c[1], zz[1], 0ull);
        ac0 = fma2_(c[2], zz[2], ac0);
        ac1 = fma2_(c[3], zz[3], ac1);
        const u64 sSum = add2_(ac0, ac1);
        float x0, x1; unpack2(sSum, x0, x1);
        yb[(size_t)t * H] = fmaf(Dh, uu[t], x0 + x1);
    }
}

extern "C" void kernel_launch(void* const* d_in, const int* in_sizes, int n_in,
                              void* d_out, int out_size)
{
    const float* u      = (const float*)d_in[0];
    const float* B_re   = (const float*)d_in[1];
    const float* C_re   = (const float*)d_in[2];
    const float* log_dt = (const float*)d_in[3];
    const float* Dp     = (const float*)d_in[4];
    float* y = (float*)d_out;

    s4_precomp<<<H, NST>>>(B_re, C_re, log_dt);
    s4_fused<<<NCOL * NGRP, 256>>>(u, Dp, y);
}

// round 10
// speedup vs baseline: 3.0690x; 1.0172x over previous
#include <cuda_runtime.h>
#include <math.h>

#define BATCH  2
#define SEQLEN 2048
#define H      512
#define NST    64
#define M      6           // virtual (compressed) modes
#define MP     3           // mode pairs (f32x2)
#define TCH    32          // timesteps per chunk (= per warp)
#define NWARP  8           // warps per CTA = chunks per group
#define NGRP   8           // chunk groups per (b,hw) column
#define NCOL   (BATCH * 16) // 32 columns; column = (b, hw)

typedef unsigned long long u64;

// compressed coefficient tables, pair-packed, [pair j][h]
__device__ u64 g_a2[MP * H];
__device__ u64 g_c2[MP * H];
__device__ u64 g_q2[MP * H];   // q   = a^TCH
__device__ u64 g_qi2[MP * H];  // qi8 = a^(-TCH*NWARP) = q^-8
// per-group aggregates: [col][g][j][lane]
__device__ u64 g_R[NCOL * NGRP * MP * 32];
// one flag per (col, g), padded to 128B
__device__ int g_flag[NCOL * NGRP * 32];

// Chebyshev nodes (M=6) over [rsqrt(2), rsqrt(65/64)]
__constant__ float f_node[M] = {
    0.987418f, 0.950516f, 0.886597f, 0.812789f, 0.748868f, 0.711966f
};

__device__ __forceinline__ u64 pack2(float lo, float hi) {
    u64 r; asm("mov.b64 %0, {%1, %2};" : "=l"(r) : "f"(lo), "f"(hi)); return r;
}
__device__ __forceinline__ void unpack2(u64 v, float& lo, float& hi) {
    asm("mov.b64 {%0, %1}, %2;" : "=f"(lo), "=f"(hi) : "l"(v));
}
__device__ __forceinline__ u64 fma2_(u64 a, u64 b, u64 c) {
    u64 d; asm("fma.rn.f32x2 %0, %1, %2, %3;" : "=l"(d) : "l"(a), "l"(b), "l"(c)); return d;
}
__device__ __forceinline__ u64 mul2_(u64 a, u64 b) {
    u64 d; asm("mul.rn.f32x2 %0, %1, %2;" : "=l"(d) : "l"(a), "l"(b)); return d;
}
__device__ __forceinline__ u64 add2_(u64 a, u64 b) {
    u64 d; asm("add.rn.f32x2 %0, %1, %2;" : "=l"(d) : "l"(a), "l"(b)); return d;
}
__device__ __forceinline__ int ld_acq(const int* p) {
    int v; asm volatile("ld.acquire.gpu.s32 %0, [%1];" : "=r"(v) : "l"(p) : "memory"); return v;
}
__device__ __forceinline__ void st_rel(int* p, int v) {
    asm volatile("st.release.gpu.s32 [%0], %1;" :: "l"(p), "r"(v) : "memory");
}

// out = base^e (e in [0,7]) per pair, repeated squaring
__device__ __forceinline__ void pow3(const u64* base, int e, u64* out) {
    u64 p0 = pack2(1.0f, 1.0f), p1 = p0, p2 = p0;
    u64 b0 = base[0], b1 = base[1], b2 = base[2];
    if (e & 1) { p0 = mul2_(p0, b0); p1 = mul2_(p1, b1); p2 = mul2_(p2, b2); }
    b0 = mul2_(b0, b0); b1 = mul2_(b1, b1); b2 = mul2_(b2, b2);
    if (e & 2) { p0 = mul2_(p0, b0); p1 = mul2_(p1, b1); p2 = mul2_(p2, b2); }
    b0 = mul2_(b0, b0); b1 = mul2_(b1, b1); b2 = mul2_(b2, b2);
    if (e & 4) { p0 = mul2_(p0, b0); p1 = mul2_(p1, b1); p2 = mul2_(p2, b2); }
    out[0] = p0; out[1] = p1; out[2] = p2;
}

// ---------------------------------------------------------------- precompute
// One block per channel h; all float. Also resets carry flags.
__global__ void s4_precomp(const float* __restrict__ B_re,
                           const float* __restrict__ C_re,
                           const float* __restrict__ log_dt)
{
    __shared__ float sc[M][NST + 1];
    __shared__ float sa[M], sq[M], sqi[M], scc[M];

    const int n = threadIdx.x;      // 0..63 (true mode)
    const int h = blockIdx.x;

    if (h == 0) {
        for (int i = n; i < NCOL * NGRP; i += NST)
            g_flag[i * 32] = 0;
    }

    const float delta = expf(log_dt[h]);
    const float An = rsqrtf(1.0f + (float)(n + 1) * (1.0f / 64.0f));
    const float cn = expm1f(delta * An) * B_re[n] * delta * C_re[n];

#pragma unroll
    for (int m = 0; m < M; ++m) {
        float num = 1.0f, den = 1.0f;
#pragma unroll
        for (int i = 0; i < M; ++i) {
            if (i == m) continue;
            num *= (An - f_node[i]);
            den *= (f_node[m] - f_node[i]);
        }
        sc[m][n] = cn * (num / den);
    }
    __syncthreads();

    if (n < M) {
        float s = 0.0f;
#pragma unroll
        for (int i = 0; i < NST; ++i) s += sc[n][i];
        scc[n] = s;
        const float dAm = delta * f_node[n];
        sa[n]  = expf(dAm);
        sq[n]  = expf(dAm * (float)TCH);
        sqi[n] = expf(-dAm * (float)(TCH * NWARP));
    }
    __syncthreads();

    if (n < MP) {
        g_a2[n * H + h]  = pack2(sa[2 * n],  sa[2 * n + 1]);
        g_c2[n * H + h]  = pack2(scc[2 * n], scc[2 * n + 1]);
        g_q2[n * H + h]  = pack2(sq[2 * n],  sq[2 * n + 1]);
        g_qi2[n * H + h] = pack2(sqi[2 * n], sqi[2 * n + 1]);
    }
}

// ------------------------------------------------------------------ fused
// CTA = (column, group); warp w = chunk g*8+w. ONE __syncthreads total.
// Publish: warp 7 add-tree over pre-scaled sEq (q^{7-i} E_i).
// Receive: EVERY warp independently — parallel lane flag-polls, fixed
// unrolled predicated q^8-Horner (T = q8^{7-g} S), then S = T * qi8^{7-g}.
__global__ __launch_bounds__(256, 2)
void s4_fused(const float* __restrict__ u,
              const float* __restrict__ Dp,
              float* __restrict__ y)
{
    __shared__ u64 sE [NWARP][MP][32];
    __shared__ u64 sEq[NWARP][MP][32];

    const int col  = blockIdx.x & (NCOL - 1);   // (b, hw)
    const int g    = blockIdx.x >> 5;           // group; lower g = lower bid
    const int w    = threadIdx.x >> 5;
    const int lane = threadIdx.x & 31;
    const int b    = col >> 4;
    const int h    = (col & 15) * 32 + lane;

    u64 a[MP], c[MP], q[MP];
#pragma unroll
    for (int j = 0; j < MP; ++j) {
        a[j] = g_a2[j * H + h];
        c[j] = g_c2[j * H + h];
        q[j] = g_q2[j * H + h];
    }
    const float Dh = Dp[h];

    const int chunk = g * NWARP + w;
    const size_t base = ((size_t)b * SEQLEN + (size_t)chunk * TCH) * H + h;
    const float* ub = u + base;

    // whole chunk of u into registers (32 coalesced LDGs, MLP=32)
    float uu[TCH];
#pragma unroll
    for (int t = 0; t < TCH; ++t) uu[t] = ub[(size_t)t * H];

    // local zero-seed scan -> E (chunk impulse state)
    u64 z[MP] = {0ull, 0ull, 0ull};
#pragma unroll
    for (int t = 0; t < TCH; ++t) {
        const u64 ubb = pack2(uu[t], uu[t]);
        z[0] = fma2_(a[0], z[0], ubb);
        z[1] = fma2_(a[1], z[1], ubb);
        z[2] = fma2_(a[2], z[2], ubb);
    }

    // stage E and q^{7-w} * E (pre-scaled for the publish add-tree)
    u64 qw7[MP];
    pow3(q, (NWARP - 1) - w, qw7);
#pragma unroll
    for (int j = 0; j < MP; ++j) {
        sE [w][j][lane] = z[j];
        sEq[w][j][lane] = mul2_(qw7[j], z[j]);
    }
    __syncthreads();    // the ONLY block-wide sync

    // warp 7: publish R_g = sum_i q^{7-i} E_i via add-tree (MLP'd LDS)
    if (w == NWARP - 1 && g < NGRP - 1) {
        u64* op = g_R + ((size_t)(col * NGRP + g) * MP) * 32 + lane;
#pragma unroll
        for (int j = 0; j < MP; ++j) {
            const u64 s01 = add2_(sEq[0][j][lane], sEq[1][j][lane]);
            const u64 s23 = add2_(sEq[2][j][lane], sEq[3][j][lane]);
            const u64 s45 = add2_(sEq[4][j][lane], sEq[5][j][lane]);
            const u64 s67 = add2_(sEq[6][j][lane], sEq[7][j][lane]);
            op[(size_t)j * 32] = add2_(add2_(s01, s23), add2_(s45, s67));
        }
        __syncwarp();
        if (lane == 0) st_rel(&g_flag[(col * NGRP + g) * 32], 1);
    }

    // P_w = sum_{i<w} q^{w-1-i} E_i  (intra-group Horner over smem)
    u64 P[MP] = {0ull, 0ull, 0ull};
    for (int i = 0; i < w; ++i) {
#pragma unroll
        for (int j = 0; j < MP; ++j)
            P[j] = fma2_(q[j], P[j], sE[i][j][lane]);
    }
    u64 qp[MP];
    pow3(q, w, qp);

    // per-warp receive: S = sum_{g2<g} q8^{g-1-g2} R_{g2}
    u64 S[MP] = {0ull, 0ull, 0ull};
    if (g > 0) {
        // parallel flag polls: lane i waits on flag i
        if (lane < g) {
            const int* fp = &g_flag[(col * NGRP + lane) * 32];
            while (ld_acq(fp) == 0) { __nanosleep(20); }
        }
        __syncwarp();

        u64 q8[MP];
#pragma unroll
        for (int j = 0; j < MP; ++j) {
            const u64 q2v = mul2_(q[j], q[j]);
            const u64 q4v = mul2_(q2v, q2v);
            q8[j] = mul2_(q4v, q4v);
        }
        // fixed unrolled predicated Horner: T = sum_{g2=0}^{6} q8^{6-g2} V_{g2},
        // V = R if g2<g else 0  =>  T = q8^{7-g} * S
        u64 T[MP] = {0ull, 0ull, 0ull};
#pragma unroll
        for (int g2 = 0; g2 < NGRP - 1; ++g2) {
            u64 v0 = 0ull, v1 = 0ull, v2 = 0ull;
            if (g2 < g) {
                const u64* rp = g_R + ((size_t)(col * NGRP + g2) * MP) * 32 + lane;
                v0 = rp[0 * 32];
                v1 = rp[1 * 32];
                v2 = rp[2 * 32];
            }
            T[0] = fma2_(q8[0], T[0], v0);
            T[1] = fma2_(q8[1], T[1], v1);
            T[2] = fma2_(q8[2], T[2], v2);
        }
        // S = T * qi8^{7-g}
        u64 qi8[MP];
#pragma unroll
        for (int j = 0; j < MP; ++j) qi8[j] = g_qi2[j * H + h];
        u64 pw[MP];
        pow3(qi8, (NGRP - 1) - g, pw);
#pragma unroll
        for (int j = 0; j < MP; ++j) S[j] = mul2_(T[j], pw[j]);
    }

    // seed = q^w * S + P_w, then output scan (writes y exactly once)
    u64 zz[MP];
#pragma unroll
    for (int j = 0; j < MP; ++j) zz[j] = fma2_(qp[j], S[j], P[j]);

    float* yb = y + base;
#pragma unroll
    for (int t = 0; t < TCH; ++t) {
        const u64 ubb = pack2(uu[t], uu[t]);
        zz[0] = fma2_(a[0], zz[0], ubb);
        zz[1] = fma2_(a[1], zz[1], ubb);
        zz[2] = fma2_(a[2], zz[2], ubb);
        u64 ac0 = fma2_(c[0], zz[0], 0ull);
        u64 ac1 = fma2_(c[1], zz[1], 0ull);
        ac0 = fma2_(c[2], zz[2], ac0);
        const u64 sSum = add2_(ac0, ac1);
        float x0, x1; unpack2(sSum, x0, x1);
        yb[(size_t)t * H] = fmaf(Dh, uu[t], x0 + x1);
    }
}

extern "C" void kernel_launch(void* const* d_in, const int* in_sizes, int n_in,
                              void* d_out, int out_size)
{
    const float* u      = (const float*)d_in[0];
    const float* B_re   = (const float*)d_in[1];
    const float* C_re   = (const float*)d_in[2];
    const float* log_dt = (const float*)d_in[3];
    const float* Dp     = (const float*)d_in[4];
    float* y = (float*)d_out;

    s4_precomp<<<H, NST>>>(B_re, C_re, log_dt);
    s4_fused<<<NCOL * NGRP, 256>>>(u, Dp, y);
}